// round 15
// baseline (speedup 1.0000x reference)
#include <cuda_runtime.h>
#include <cuda.h>
#include <cuda_bf16.h>
#include <cstdint>

namespace {

constexpr int   HW    = 36864;        // 192*192
constexpr float SCALE = 0.17677669529663687f;  // 1/sqrt(32)

// dynamic smem layout (float/word units)
constexpr int RAW  = 0;      // 2048 words: TMA staging (Q, then V)
constexpr int TQH  = 2048;   // Q hi tile: 64 x 20
constexpr int TQL  = 3328;
constexpr int TKH  = 4608;
constexpr int TKL  = 5888;
constexpr int TVH  = 7168;   // V hi tile: 32 x 36; [TVH,TVH+2048) doubles as K staging
constexpr int TVL  = 8316;
constexpr int MBAR = 9464;   // bar0 @9464, bar1 @9466
constexpr int SMEM_BYTES = 9468 * 4;  // 37872 B -> 6 CTAs/SM

__device__ __forceinline__ uint32_t s2u(const void* p) {
  uint32_t a;
  asm("{ .reg .u64 t; cvta.to.shared.u64 t, %1; cvt.u32.u64 %0, t; }" : "=r"(a) : "l"(p));
  return a;
}
// pack truncated-bf16 pair: low half = top16(f0), high half = top16(f1) — one PRMT
__device__ __forceinline__ uint32_t packhi(float f0, float f1) {
  uint32_t r;
  asm("prmt.b32 %0, %1, %2, 0x7632;"
      : "=r"(r) : "r"(__float_as_uint(f0)), "r"(__float_as_uint(f1)));
  return r;
}
// truncate fp32 to bf16-representable value (exact split: f = th(f) + (f - th(f)))
__device__ __forceinline__ float th(float f) {
  return __uint_as_float(__float_as_uint(f) & 0xFFFF0000u);
}
__device__ __forceinline__ uint32_t pack2(float lo, float hi) {
  uint32_t r;
  asm("cvt.rn.bf16x2.f32 %0, %1, %2;" : "=r"(r) : "f"(hi), "f"(lo));
  return r;
}
__device__ __forceinline__ void mma_bf16(float* c, const uint32_t* a,
                                         uint32_t b0, uint32_t b1) {
  asm volatile(
      "mma.sync.aligned.m16n8k16.row.col.f32.bf16.bf16.f32 "
      "{%0,%1,%2,%3}, {%4,%5,%6,%7}, {%8,%9}, {%0,%1,%2,%3};"
      : "+f"(c[0]), "+f"(c[1]), "+f"(c[2]), "+f"(c[3])
      : "r"(a[0]), "r"(a[1]), "r"(a[2]), "r"(a[3]), "r"(b0), "r"(b1));
}
__device__ __forceinline__ int qkw(int r, int w) {
  return r * 20 + (w ^ (((r >> 3) & 3) << 2));
}
__device__ __forceinline__ float felem(float4 a, int j) {
  return (j == 0) ? a.x : (j == 1) ? a.y : (j == 2) ? a.z : a.w;
}
__device__ __forceinline__ void bar_init(uint32_t bar, uint32_t cnt) {
  asm volatile("mbarrier.init.shared.b64 [%0], %1;" :: "r"(bar), "r"(cnt) : "memory");
}
__device__ __forceinline__ void bar_expect(uint32_t bar, uint32_t bytes) {
  asm volatile("mbarrier.arrive.expect_tx.shared.b64 _, [%0], %1;"
               :: "r"(bar), "r"(bytes) : "memory");
}
__device__ __forceinline__ void bar_wait(uint32_t bar, uint32_t parity) {
  uint32_t done;
  asm volatile(
      "{\n\t.reg .pred p;\n\t"
      "mbarrier.try_wait.parity.acquire.cta.shared::cta.b64 p, [%1], %2;\n\t"
      "selp.b32 %0, 1, 0, p;\n\t}"
      : "=r"(done) : "r"(bar), "r"(parity) : "memory");
  if (!done) {
    asm volatile(
        "{\n\t.reg .pred P1;\n\t"
        "W_%=:\n\t"
        "mbarrier.try_wait.parity.acquire.cta.shared::cta.b64 P1, [%0], %1, 0x989680;\n\t"
        "@P1 bra.uni D_%=;\n\t"
        "bra.uni W_%=;\n\t"
        "D_%=:\n\t}"
        :: "r"(bar), "r"(parity) : "memory");
  }
}
__device__ __forceinline__ void tma3d(uint32_t dst, const CUtensorMap* map,
                                      int x, int y, int z, uint32_t bar) {
  asm volatile(
      "cp.async.bulk.tensor.3d.shared::cta.global.tile.mbarrier::complete_tx::bytes "
      "[%0], [%1, {%2, %3, %4}], [%5];"
      :: "r"(dst), "l"(map), "r"(x), "r"(y), "r"(z), "r"(bar) : "memory");
}
__device__ __forceinline__ void tma3d_store(const CUtensorMap* map,
                                            int x, int y, int z, uint32_t src) {
  asm volatile(
      "cp.async.bulk.tensor.3d.global.shared::cta.tile.bulk_group "
      "[%0, {%1, %2, %3}], [%4];"
      :: "l"(map), "r"(x), "r"(y), "r"(z), "r"(src) : "memory");
}

}  // namespace

// fragment-ordered mask: [win][warp(4)][j(8)][lane(32)][4 floats]
__device__ float g_maskf[576 * 4096];

__global__ void repack_mask(const float* __restrict__ mask) {
  const int win = blockIdx.x;
  const int tid = threadIdx.x;
  const int wid = tid >> 5;
  const int lid = tid & 31;
  const int g = lid >> 2;
  const int t = lid & 3;
  const float* __restrict__ src = mask + win * 4096;
  float* __restrict__ dst = g_maskf + win * 4096 + wid * 1024;
#pragma unroll
  for (int j = 0; j < 8; j++) {
    const int c0 = 8 * j + 2 * t;
    float4 m;
    m.x = src[(wid * 16 + g) * 64 + c0];
    m.y = src[(wid * 16 + g) * 64 + c0 + 1];
    m.z = src[(wid * 16 + 8 + g) * 64 + c0];
    m.w = src[(wid * 16 + 8 + g) * 64 + c0 + 1];
    *(float4*)(dst + j * 128 + lid * 4) = m;
  }
}

__global__ __launch_bounds__(128, 6) void winattn_tma7(
    const __grid_constant__ CUtensorMap mapQ,
    const __grid_constant__ CUtensorMap mapKV,
    const __grid_constant__ CUtensorMap mapO) {
  extern __shared__ float dyn[];
  float* __restrict__ raw = dyn + RAW;
  uint32_t* __restrict__ sm = (uint32_t*)dyn;   // tiles addressed by absolute word offset

  const int tid = threadIdx.x;
  const int wid = tid >> 5;
  const int lid = tid & 31;

  // block decode: 48 consecutive CTAs (8 b x 6 d) share one mask window (L2 reuse)
  const int blk = blockIdx.x;
  const int win = blk / 48;
  const int rem = blk % 48;
  const int b = rem / 6;
  const int d = rem % 6;
  const int u = win / 24;
  const int v = win % 24;
  const int zc = b * 192 + d * 32;

  const uint32_t bar0 = s2u(dyn + MBAR);
  const uint32_t bar1 = s2u(dyn + MBAR + 2);
  const uint32_t rawA = s2u(raw);
  if (tid == 0) { bar_init(bar0, 1); bar_init(bar1, 1); }
  __syncthreads();

  // ---- issue Q -> raw and K -> V-tile region concurrently ----
  if (tid == 0) {
    bar_expect(bar0, 8192);
    tma3d(rawA, &mapQ, v * 8, u * 8, zc, bar0);
    bar_expect(bar1, 8192);
    tma3d(s2u(dyn + TVH), &mapKV, v * 8, u * 8, zc, bar1);
  }

  // ---------------- phase 1: convert Q (raw) -> TQH/TQL ----------------
  bar_wait(bar0, 0);
#pragma unroll
  for (int it = 0; it < 2; it++) {
    const int p  = it * 128 + tid;       // 0..255
    const int cw = p >> 4;               // word index = ci/2 (0..15)
    const int h  = (p >> 1) & 7;
    const int wq = p & 1;
    const int n0 = h * 8 + wq * 4;
    const int ro = (2 * cw) * 64 + h * 8 + wq * 4;
    const float4 a0 = *(const float4*)(raw + ro);
    const float4 a1 = *(const float4*)(raw + ro + 64);
#pragma unroll
    for (int j = 0; j < 4; j++) {
      const float f0 = felem(a0, j), f1 = felem(a1, j);
      const int w = qkw(n0 + j, cw);
      sm[TQH + w] = packhi(f0, f1);
      sm[TQL + w] = pack2(f0 - th(f0), f1 - th(f1));
    }
  }
  __syncthreads();   // raw free -> issue V load

  if (tid == 0) {
    bar_expect(bar0, 8192);
    tma3d(rawA, &mapKV, v * 8, u * 8, 1536 + zc, bar0);
  }

  // ---------------- phase 2: convert K (V-tile region) -> TKH/TKL ----------------
  bar_wait(bar1, 0);
  {
    const float* __restrict__ kraw = dyn + TVH;
#pragma unroll
    for (int it = 0; it < 2; it++) {
      const int p  = it * 128 + tid;
      const int cw = p >> 4;
      const int h  = (p >> 1) & 7;
      const int wq = p & 1;
      const int n0 = h * 8 + wq * 4;
      const int ro = (2 * cw) * 64 + h * 8 + wq * 4;
      const float4 a0 = *(const float4*)(kraw + ro);
      const float4 a1 = *(const float4*)(kraw + ro + 64);
#pragma unroll
      for (int j = 0; j < 4; j++) {
        const float f0 = felem(a0, j), f1 = felem(a1, j);
        const int w = qkw(n0 + j, cw);
        sm[TKH + w] = packhi(f0, f1);
        sm[TKL + w] = pack2(f0 - th(f0), f1 - th(f1));
      }
    }
  }
  __syncthreads();   // K staging reads done -> V tiles may be written

  // ---------------- phase 3: convert V (raw) -> TVH/TVL ----------------
  bar_wait(bar0, 1);
#pragma unroll
  for (int it = 0; it < 4; it++) {
    const int p  = it * 128 + tid;       // 0..511
    const int ci = p >> 4;
    const int h  = (p >> 1) & 7;
    const int wq = p & 1;
    const int n0 = h * 8 + wq * 4;
    const float4 a = *(const float4*)(raw + ci * 64 + h * 8 + wq * 4);
    uint2 hp, lp;
    hp.x = packhi(a.x, a.y);
    hp.y = packhi(a.z, a.w);
    lp.x = pack2(a.x - th(a.x), a.y - th(a.y));
    lp.y = pack2(a.z - th(a.z), a.w - th(a.w));
    *(uint2*)&sm[TVH + ci * 36 + (n0 >> 1)] = hp;
    *(uint2*)&sm[TVL + ci * 36 + (n0 >> 1)] = lp;
  }
  __syncthreads();

  const int g  = lid >> 2;   // 0..7
  const int t  = lid & 3;    // 0..3
  const int m0 = wid * 16;

  // ================= A-fragments =================================================
  uint32_t aqh[2][4], aql[2][4];
#pragma unroll
  for (int ks = 0; ks < 2; ks++) {
    aqh[ks][0] = sm[TQH + qkw(m0 + g,     ks * 8 + t)];
    aqh[ks][1] = sm[TQH + qkw(m0 + g + 8, ks * 8 + t)];
    aqh[ks][2] = sm[TQH + qkw(m0 + g,     ks * 8 + 4 + t)];
    aqh[ks][3] = sm[TQH + qkw(m0 + g + 8, ks * 8 + 4 + t)];
    aql[ks][0] = sm[TQL + qkw(m0 + g,     ks * 8 + t)];
    aql[ks][1] = sm[TQL + qkw(m0 + g + 8, ks * 8 + t)];
    aql[ks][2] = sm[TQL + qkw(m0 + g,     ks * 8 + 4 + t)];
    aql[ks][3] = sm[TQL + qkw(m0 + g + 8, ks * 8 + 4 + t)];
  }

  // ================= QK^T : warp owns rows m0..m0+15 =============================
  float c[8][4];
#pragma unroll
  for (int j = 0; j < 8; j++)
#pragma unroll
    for (int i = 0; i < 4; i++) c[j][i] = 0.f;

#pragma unroll
  for (int j = 0; j < 8; j++) {          // n-tile: cols 8j..8j+7
    const int rb = j * 8 + g;
#pragma unroll
    for (int ks = 0; ks < 2; ks++) {
      const uint32_t bh0 = sm[TKH + qkw(rb, ks * 8 + t)];
      const uint32_t bh1 = sm[TKH + qkw(rb, ks * 8 + 4 + t)];
      const uint32_t bl0 = sm[TKL + qkw(rb, ks * 8 + t)];
      const uint32_t bl1 = sm[TKL + qkw(rb, ks * 8 + 4 + t)];
      mma_bf16(c[j], aqh[ks], bh0, bh1);
      mma_bf16(c[j], aqh[ks], bl0, bl1);
      mma_bf16(c[j], aql[ks], bh0, bh1);
    }
  }

  // ===== softmax: mask from fragment-ordered global buffer (dense LDG.128) ======
  const float4* __restrict__ mw =
      (const float4*)(g_maskf + win * 4096 + wid * 1024) + lid;
  float sum0 = 0.f, sum1 = 0.f;
#pragma unroll
  for (int j = 0; j < 8; j++) {
    const float4 m = mw[j * 32];
    float e;
    e = __expf(fmaf(c[j][0], SCALE, m.x)); c[j][0] = e; sum0 += e;
    e = __expf(fmaf(c[j][1], SCALE, m.y)); c[j][1] = e; sum0 += e;
    e = __expf(fmaf(c[j][2], SCALE, m.z)); c[j][2] = e; sum1 += e;
    e = __expf(fmaf(c[j][3], SCALE, m.w)); c[j][3] = e; sum1 += e;
  }
  sum0 += __shfl_xor_sync(0xffffffffu, sum0, 1);
  sum0 += __shfl_xor_sync(0xffffffffu, sum0, 2);
  sum1 += __shfl_xor_sync(0xffffffffu, sum1, 1);
  sum1 += __shfl_xor_sync(0xffffffffu, sum1, 2);
  const float inv0 = 1.0f / sum0;
  const float inv1 = 1.0f / sum1;

  // P fragments (S accumulator layout == PV A-fragment layout), truncated hi/lo
  uint32_t aph[4][4], apl[4][4];
#pragma unroll
  for (int ks = 0; ks < 4; ks++) {
    const float* p0 = c[2 * ks];
    const float* p1 = c[2 * ks + 1];
    aph[ks][0] = packhi(p0[0], p0[1]);
    aph[ks][1] = packhi(p0[2], p0[3]);
    aph[ks][2] = packhi(p1[0], p1[1]);
    aph[ks][3] = packhi(p1[2], p1[3]);
    apl[ks][0] = pack2(p0[0] - th(p0[0]), p0[1] - th(p0[1]));
    apl[ks][1] = pack2(p0[2] - th(p0[2]), p0[3] - th(p0[3]));
    apl[ks][2] = pack2(p1[0] - th(p1[0]), p1[1] - th(p1[1]));
    apl[ks][3] = pack2(p1[2] - th(p1[2]), p1[3] - th(p1[3]));
  }
  __syncthreads();   // all warps past tile reads before sO overwrites Q region

  // ================= O = P V =====================================================
  float o[4][4];
#pragma unroll
  for (int jn = 0; jn < 4; jn++)
#pragma unroll
    for (int i = 0; i < 4; i++) o[jn][i] = 0.f;

#pragma unroll
  for (int jn = 0; jn < 4; jn++) {       // channel tile 8jn..8jn+7
    const int rv = (jn * 8 + g) * 36;
#pragma unroll
    for (int ks = 0; ks < 4; ks++) {     // key step 16ks..16ks+15
      const uint32_t bh0 = sm[TVH + rv + ks * 8 + t];
      const uint32_t bh1 = sm[TVH + rv + ks * 8 + 4 + t];
      const uint32_t bl0 = sm[TVL + rv + ks * 8 + t];
      const uint32_t bl1 = sm[TVL + rv + ks * 8 + 4 + t];
      mma_bf16(o[jn], aph[ks], bh0, bh1);
      mma_bf16(o[jn], aph[ks], bl0, bl1);
      mma_bf16(o[jn], apl[ks], bh0, bh1);
    }
  }

  // ===== stage O dense [c][h][w] fp32 (plain layout, TMA store source) ===========
  float* __restrict__ sO = dyn + TQH;    // words [2048..4096), Q tiles dead
#pragma unroll
  for (int jn = 0; jn < 4; jn++) {
    const int ch = jn * 8 + 2 * t;
#pragma unroll
    for (int bb = 0; bb < 2; bb++) {
      sO[(ch + bb) * 64 + m0 + g]     = o[jn][bb] * inv0;
      sO[(ch + bb) * 64 + m0 + g + 8] = o[jn][2 + bb] * inv1;
    }
  }
  __syncthreads();

  // ================= TMA store O =================================================
  if (tid == 0) {
    asm volatile("fence.proxy.async.shared::cta;" ::: "memory");
    tma3d_store(&mapO, v * 8, u * 8, zc, s2u(sO));
    asm volatile("cp.async.bulk.commit_group;" ::: "memory");
    asm volatile("cp.async.bulk.wait_group 0;" ::: "memory");
  }
}

typedef CUresult (*EncodeFn)(CUtensorMap*, CUtensorMapDataType, cuuint32_t, void*,
                             const cuuint64_t*, const cuuint64_t*, const cuuint32_t*,
                             const cuuint32_t*, CUtensorMapInterleave, CUtensorMapSwizzle,
                             CUtensorMapL2promotion, CUtensorMapFloatOOBfill);

extern "C" void kernel_launch(void* const* d_in, const int* in_sizes, int n_in,
                              void* d_out, int out_size) {
  const float* kv = nullptr;
  const float* q = nullptr;
  const float* mask = nullptr;
  for (int i = 0; i < n_in; i++) {
    if (in_sizes[i] == 113246208) kv = (const float*)d_in[i];
    else if (in_sizes[i] == 56623104) q = (const float*)d_in[i];
    else if (in_sizes[i] == 2359296) mask = (const float*)d_in[i];
  }
  if (!kv)   kv   = (const float*)d_in[0];
  if (!q)    q    = (const float*)d_in[1];
  if (!mask) mask = (const float*)d_in[2];

  EncodeFn encode = nullptr;
  cudaDriverEntryPointQueryResult qres;
  cudaGetDriverEntryPoint("cuTensorMapEncodeTiled", (void**)&encode,
                          cudaEnableDefault, &qres);

  cuuint64_t strides[2] = {192 * 4ull, (cuuint64_t)HW * 4ull};
  cuuint32_t box[3]     = {8, 8, 32};
  cuuint32_t es[3]      = {1, 1, 1};

  CUtensorMap mapQ{}, mapKV{}, mapO{};
  {
    cuuint64_t dims[3] = {192, 192, 1536};
    encode(&mapQ, CU_TENSOR_MAP_DATA_TYPE_FLOAT32, 3, (void*)q,
           dims, strides, box, es,
           CU_TENSOR_MAP_INTERLEAVE_NONE, CU_TENSOR_MAP_SWIZZLE_NONE,
           CU_TENSOR_MAP_L2_PROMOTION_L2_128B, CU_TENSOR_MAP_FLOAT_OOB_FILL_NONE);
  }
  {
    cuuint64_t dims[3] = {192, 192, 3072};
    encode(&mapKV, CU_TENSOR_MAP_DATA_TYPE_FLOAT32, 3, (void*)kv,
           dims, strides, box, es,
           CU_TENSOR_MAP_INTERLEAVE_NONE, CU_TENSOR_MAP_SWIZZLE_NONE,
           CU_TENSOR_MAP_L2_PROMOTION_L2_128B, CU_TENSOR_MAP_FLOAT_OOB_FILL_NONE);
  }
  {
    cuuint64_t dims[3] = {192, 192, 1536};
    encode(&mapO, CU_TENSOR_MAP_DATA_TYPE_FLOAT32, 3, d_out,
           dims, strides, box, es,
           CU_TENSOR_MAP_INTERLEAVE_NONE, CU_TENSOR_MAP_SWIZZLE_NONE,
           CU_TENSOR_MAP_L2_PROMOTION_L2_128B, CU_TENSOR_MAP_FLOAT_OOB_FILL_NONE);
  }

  repack_mask<<<576, 128>>>(mask);
  cudaFuncSetAttribute(winattn_tma7, cudaFuncAttributeMaxDynamicSharedMemorySize,
                       SMEM_BYTES);
  winattn_tma7<<<27648, 128, SMEM_BYTES>>>(mapQ, mapKV, mapO);
}

// round 16
// speedup vs baseline: 1.2738x; 1.2738x over previous
#include <cuda_runtime.h>
#include <cuda.h>
#include <cuda_bf16.h>
#include <cstdint>

namespace {

constexpr int   HW    = 36864;        // 192*192
constexpr float SCALE = 0.17677669529663687f;  // 1/sqrt(32)

// dynamic smem layout (float/word units)
constexpr int RAW  = 0;      // 2048 words: TMA staging buffer (Q, then K, then V)
constexpr int TQH  = 2048;   // Q hi tile: 64 x 20
constexpr int TQL  = 3328;
constexpr int TKH  = 4608;
constexpr int TKL  = 5888;
constexpr int TVH  = 7168;   // V hi tile: 32 x 36 (1148)
constexpr int TVL  = 8316;
constexpr int MBAR = 9464;   // 2 words
constexpr int SMEM_BYTES = 9466 * 4;  // 37864 B -> 6 CTAs/SM

__device__ __forceinline__ uint32_t s2u(const void* p) {
  uint32_t a;
  asm("{ .reg .u64 t; cvta.to.shared.u64 t, %1; cvt.u32.u64 %0, t; }" : "=r"(a) : "l"(p));
  return a;
}
// pack truncated-bf16 pair: low half = top16(f0), high half = top16(f1) — one PRMT
__device__ __forceinline__ uint32_t packhi(float f0, float f1) {
  uint32_t r;
  asm("prmt.b32 %0, %1, %2, 0x7632;"
      : "=r"(r) : "r"(__float_as_uint(f0)), "r"(__float_as_uint(f1)));
  return r;
}
// truncate fp32 to bf16-representable value (exact split: f = th(f) + (f - th(f)))
__device__ __forceinline__ float th(float f) {
  return __uint_as_float(__float_as_uint(f) & 0xFFFF0000u);
}
__device__ __forceinline__ uint32_t pack2(float lo, float hi) {
  uint32_t r;
  asm("cvt.rn.bf16x2.f32 %0, %1, %2;" : "=r"(r) : "f"(hi), "f"(lo));
  return r;
}
__device__ __forceinline__ void mma_bf16(float* c, const uint32_t* a,
                                         uint32_t b0, uint32_t b1) {
  asm volatile(
      "mma.sync.aligned.m16n8k16.row.col.f32.bf16.bf16.f32 "
      "{%0,%1,%2,%3}, {%4,%5,%6,%7}, {%8,%9}, {%0,%1,%2,%3};"
      : "+f"(c[0]), "+f"(c[1]), "+f"(c[2]), "+f"(c[3])
      : "r"(a[0]), "r"(a[1]), "r"(a[2]), "r"(a[3]), "r"(b0), "r"(b1));
}
__device__ __forceinline__ int qkw(int r, int w) {
  return r * 20 + (w ^ (((r >> 3) & 3) << 2));
}
__device__ __forceinline__ float felem(float4 a, int j) {
  return (j == 0) ? a.x : (j == 1) ? a.y : (j == 2) ? a.z : a.w;
}
__device__ __forceinline__ void bar_init(uint32_t bar, uint32_t cnt) {
  asm volatile("mbarrier.init.shared.b64 [%0], %1;" :: "r"(bar), "r"(cnt) : "memory");
}
__device__ __forceinline__ void bar_expect(uint32_t bar, uint32_t bytes) {
  asm volatile("mbarrier.arrive.expect_tx.shared.b64 _, [%0], %1;"
               :: "r"(bar), "r"(bytes) : "memory");
}
__device__ __forceinline__ void bar_wait(uint32_t bar, uint32_t parity) {
  uint32_t done;
  asm volatile(
      "{\n\t.reg .pred p;\n\t"
      "mbarrier.try_wait.parity.acquire.cta.shared::cta.b64 p, [%1], %2;\n\t"
      "selp.b32 %0, 1, 0, p;\n\t}"
      : "=r"(done) : "r"(bar), "r"(parity) : "memory");
  if (!done) {
    asm volatile(
        "{\n\t.reg .pred P1;\n\t"
        "W_%=:\n\t"
        "mbarrier.try_wait.parity.acquire.cta.shared::cta.b64 P1, [%0], %1, 0x989680;\n\t"
        "@P1 bra.uni D_%=;\n\t"
        "bra.uni W_%=;\n\t"
        "D_%=:\n\t}"
        :: "r"(bar), "r"(parity) : "memory");
  }
}
__device__ __forceinline__ void tma3d(uint32_t dst, const CUtensorMap* map,
                                      int x, int y, int z, uint32_t bar) {
  asm volatile(
      "cp.async.bulk.tensor.3d.shared::cta.global.tile.mbarrier::complete_tx::bytes "
      "[%0], [%1, {%2, %3, %4}], [%5];"
      :: "r"(dst), "l"(map), "r"(x), "r"(y), "r"(z), "r"(bar) : "memory");
}
__device__ __forceinline__ void tma3d_store(const CUtensorMap* map,
                                            int x, int y, int z, uint32_t src) {
  asm volatile(
      "cp.async.bulk.tensor.3d.global.shared::cta.tile.bulk_group "
      "[%0, {%1, %2, %3}], [%4];"
      :: "l"(map), "r"(x), "r"(y), "r"(z), "r"(src) : "memory");
}

}  // namespace

// fragment-ordered mask: [win][warp(4)][j(8)][lane(32)][4 floats]
__device__ float g_maskf[576 * 4096];

__global__ void repack_mask(const float* __restrict__ mask) {
  const int win = blockIdx.x;
  const int tid = threadIdx.x;
  const int wid = tid >> 5;
  const int lid = tid & 31;
  const int g = lid >> 2;
  const int t = lid & 3;
  const float* __restrict__ src = mask + win * 4096;
  float* __restrict__ dst = g_maskf + win * 4096 + wid * 1024;
#pragma unroll
  for (int j = 0; j < 8; j++) {
    const int c0 = 8 * j + 2 * t;
    float4 m;
    m.x = src[(wid * 16 + g) * 64 + c0];
    m.y = src[(wid * 16 + g) * 64 + c0 + 1];
    m.z = src[(wid * 16 + 8 + g) * 64 + c0];
    m.w = src[(wid * 16 + 8 + g) * 64 + c0 + 1];
    *(float4*)(dst + j * 128 + lid * 4) = m;
  }
}

__global__ __launch_bounds__(128, 6) void winattn_tma8(
    const __grid_constant__ CUtensorMap mapQ,
    const __grid_constant__ CUtensorMap mapKV,
    const __grid_constant__ CUtensorMap mapO) {
  extern __shared__ float dyn[];
  float* __restrict__ raw = dyn + RAW;
  uint32_t* __restrict__ sm = (uint32_t*)dyn;   // tiles addressed by absolute word offset

  const int tid = threadIdx.x;
  const int wid = tid >> 5;
  const int lid = tid & 31;

  // block decode: 48 consecutive CTAs (8 b x 6 d) share one mask window (L2 reuse)
  const int blk = blockIdx.x;
  const int win = blk / 48;
  const int rem = blk % 48;
  const int b = rem / 6;
  const int d = rem % 6;
  const int u = win / 24;
  const int v = win % 24;
  const int zc = b * 192 + d * 32;

  const uint32_t mbar = s2u(dyn + MBAR);
  const uint32_t rawA = s2u(raw);
  if (tid == 0) bar_init(mbar, 1);
  __syncthreads();

  // ---------------- phase 1: Q -> raw, convert to TQH/TQL ----------------
  if (tid == 0) {
    bar_expect(mbar, 8192);
    tma3d(rawA, &mapQ, v * 8, u * 8, zc, mbar);
  }
  bar_wait(mbar, 0);
#pragma unroll
  for (int it = 0; it < 2; it++) {
    const int p  = it * 128 + tid;       // 0..255
    const int cw = p >> 4;               // word index = ci/2 (0..15)
    const int h  = (p >> 1) & 7;
    const int wq = p & 1;
    const int n0 = h * 8 + wq * 4;
    const int ro = (2 * cw) * 64 + h * 8 + wq * 4;
    const float4 a0 = *(const float4*)(raw + ro);
    const float4 a1 = *(const float4*)(raw + ro + 64);
#pragma unroll
    for (int j = 0; j < 4; j++) {
      const float f0 = felem(a0, j), f1 = felem(a1, j);
      const int w = qkw(n0 + j, cw);
      sm[TQH + w] = packhi(f0, f1);
      sm[TQL + w] = pack2(f0 - th(f0), f1 - th(f1));
    }
  }
  __syncthreads();

  // ---------------- phase 2: K -> raw, convert to TKH/TKL ----------------
  if (tid == 0) {
    bar_expect(mbar, 8192);
    tma3d(rawA, &mapKV, v * 8, u * 8, zc, mbar);
  }
  bar_wait(mbar, 1);
#pragma unroll
  for (int it = 0; it < 2; it++) {
    const int p  = it * 128 + tid;
    const int cw = p >> 4;
    const int h  = (p >> 1) & 7;
    const int wq = p & 1;
    const int n0 = h * 8 + wq * 4;
    const int ro = (2 * cw) * 64 + h * 8 + wq * 4;
    const float4 a0 = *(const float4*)(raw + ro);
    const float4 a1 = *(const float4*)(raw + ro + 64);
#pragma unroll
    for (int j = 0; j < 4; j++) {
      const float f0 = felem(a0, j), f1 = felem(a1, j);
      const int w = qkw(n0 + j, cw);
      sm[TKH + w] = packhi(f0, f1);
      sm[TKL + w] = pack2(f0 - th(f0), f1 - th(f1));
    }
  }
  __syncthreads();

  // ---------------- phase 3: V -> raw, convert to TVH/TVL ----------------
  if (tid == 0) {
    bar_expect(mbar, 8192);
    tma3d(rawA, &mapKV, v * 8, u * 8, 1536 + zc, mbar);
  }
  bar_wait(mbar, 0);
#pragma unroll
  for (int it = 0; it < 4; it++) {
    const int p  = it * 128 + tid;       // 0..511
    const int ci = p >> 4;
    const int h  = (p >> 1) & 7;
    const int wq = p & 1;
    const int n0 = h * 8 + wq * 4;
    const float4 a = *(const float4*)(raw + ci * 64 + h * 8 + wq * 4);
    uint2 hp, lp;
    hp.x = packhi(a.x, a.y);
    hp.y = packhi(a.z, a.w);
    lp.x = pack2(a.x - th(a.x), a.y - th(a.y));
    lp.y = pack2(a.z - th(a.z), a.w - th(a.w));
    *(uint2*)&sm[TVH + ci * 36 + (n0 >> 1)] = hp;
    *(uint2*)&sm[TVL + ci * 36 + (n0 >> 1)] = lp;
  }
  __syncthreads();

  const int g  = lid >> 2;   // 0..7
  const int t  = lid & 3;    // 0..3
  const int m0 = wid * 16;

  // ================= A-fragments =================================================
  uint32_t aqh[2][4], aql[2][4];
#pragma unroll
  for (int ks = 0; ks < 2; ks++) {
    aqh[ks][0] = sm[TQH + qkw(m0 + g,     ks * 8 + t)];
    aqh[ks][1] = sm[TQH + qkw(m0 + g + 8, ks * 8 + t)];
    aqh[ks][2] = sm[TQH + qkw(m0 + g,     ks * 8 + 4 + t)];
    aqh[ks][3] = sm[TQH + qkw(m0 + g + 8, ks * 8 + 4 + t)];
    aql[ks][0] = sm[TQL + qkw(m0 + g,     ks * 8 + t)];
    aql[ks][1] = sm[TQL + qkw(m0 + g + 8, ks * 8 + t)];
    aql[ks][2] = sm[TQL + qkw(m0 + g,     ks * 8 + 4 + t)];
    aql[ks][3] = sm[TQL + qkw(m0 + g + 8, ks * 8 + 4 + t)];
  }

  // ================= QK^T : warp owns rows m0..m0+15 =============================
  float c[8][4];
#pragma unroll
  for (int j = 0; j < 8; j++)
#pragma unroll
    for (int i = 0; i < 4; i++) c[j][i] = 0.f;

#pragma unroll
  for (int j = 0; j < 8; j++) {          // n-tile: cols 8j..8j+7
    const int rb = j * 8 + g;
#pragma unroll
    for (int ks = 0; ks < 2; ks++) {
      const uint32_t bh0 = sm[TKH + qkw(rb, ks * 8 + t)];
      const uint32_t bh1 = sm[TKH + qkw(rb, ks * 8 + 4 + t)];
      const uint32_t bl0 = sm[TKL + qkw(rb, ks * 8 + t)];
      const uint32_t bl1 = sm[TKL + qkw(rb, ks * 8 + 4 + t)];
      mma_bf16(c[j], aqh[ks], bh0, bh1);
      mma_bf16(c[j], aqh[ks], bl0, bl1);
      mma_bf16(c[j], aql[ks], bh0, bh1);
    }
  }

  // ===== softmax: mask from fragment-ordered global buffer (dense LDG.128) ======
  const float4* __restrict__ mw =
      (const float4*)(g_maskf + win * 4096 + wid * 1024) + lid;
  float sum0 = 0.f, sum1 = 0.f;
#pragma unroll
  for (int j = 0; j < 8; j++) {
    const float4 m = mw[j * 32];
    float e;
    e = __expf(fmaf(c[j][0], SCALE, m.x)); c[j][0] = e; sum0 += e;
    e = __expf(fmaf(c[j][1], SCALE, m.y)); c[j][1] = e; sum0 += e;
    e = __expf(fmaf(c[j][2], SCALE, m.z)); c[j][2] = e; sum1 += e;
    e = __expf(fmaf(c[j][3], SCALE, m.w)); c[j][3] = e; sum1 += e;
  }
  sum0 += __shfl_xor_sync(0xffffffffu, sum0, 1);
  sum0 += __shfl_xor_sync(0xffffffffu, sum0, 2);
  sum1 += __shfl_xor_sync(0xffffffffu, sum1, 1);
  sum1 += __shfl_xor_sync(0xffffffffu, sum1, 2);
  const float inv0 = 1.0f / sum0;
  const float inv1 = 1.0f / sum1;

  // P fragments (S accumulator layout == PV A-fragment layout), truncated hi/lo
  uint32_t aph[4][4], apl[4][4];
#pragma unroll
  for (int ks = 0; ks < 4; ks++) {
    const float* p0 = c[2 * ks];
    const float* p1 = c[2 * ks + 1];
    aph[ks][0] = packhi(p0[0], p0[1]);
    aph[ks][1] = packhi(p0[2], p0[3]);
    aph[ks][2] = packhi(p1[0], p1[1]);
    aph[ks][3] = packhi(p1[2], p1[3]);
    apl[ks][0] = pack2(p0[0] - th(p0[0]), p0[1] - th(p0[1]));
    apl[ks][1] = pack2(p0[2] - th(p0[2]), p0[3] - th(p0[3]));
    apl[ks][2] = pack2(p1[0] - th(p1[0]), p1[1] - th(p1[1]));
    apl[ks][3] = pack2(p1[2] - th(p1[2]), p1[3] - th(p1[3]));
  }
  __syncthreads();   // all warps past tile reads before sO overwrites Q region

  // ================= O = P V =====================================================
  float o[4][4];
#pragma unroll
  for (int jn = 0; jn < 4; jn++)
#pragma unroll
    for (int i = 0; i < 4; i++) o[jn][i] = 0.f;

#pragma unroll
  for (int jn = 0; jn < 4; jn++) {       // channel tile 8jn..8jn+7
    const int rv = (jn * 8 + g) * 36;
#pragma unroll
    for (int ks = 0; ks < 4; ks++) {     // key step 16ks..16ks+15
      const uint32_t bh0 = sm[TVH + rv + ks * 8 + t];
      const uint32_t bh1 = sm[TVH + rv + ks * 8 + 4 + t];
      const uint32_t bl0 = sm[TVL + rv + ks * 8 + t];
      const uint32_t bl1 = sm[TVL + rv + ks * 8 + 4 + t];
      mma_bf16(o[jn], aph[ks], bh0, bh1);
      mma_bf16(o[jn], aph[ks], bl0, bl1);
      mma_bf16(o[jn], apl[ks], bh0, bh1);
    }
  }

  // ===== stage O dense [c][h][w] fp32 (plain layout, TMA store source) ===========
  float* __restrict__ sO = dyn + TQH;    // words [2048..4096), Q tiles dead
#pragma unroll
  for (int jn = 0; jn < 4; jn++) {
    const int ch = jn * 8 + 2 * t;
#pragma unroll
    for (int bb = 0; bb < 2; bb++) {
      sO[(ch + bb) * 64 + m0 + g]     = o[jn][bb] * inv0;
      sO[(ch + bb) * 64 + m0 + g + 8] = o[jn][2 + bb] * inv1;
    }
  }
  __syncthreads();

  // ================= TMA store O =================================================
  if (tid == 0) {
    asm volatile("fence.proxy.async.shared::cta;" ::: "memory");
    tma3d_store(&mapO, v * 8, u * 8, zc, s2u(sO));
    asm volatile("cp.async.bulk.commit_group;" ::: "memory");
    asm volatile("cp.async.bulk.wait_group 0;" ::: "memory");
  }
}

typedef CUresult (*EncodeFn)(CUtensorMap*, CUtensorMapDataType, cuuint32_t, void*,
                             const cuuint64_t*, const cuuint64_t*, const cuuint32_t*,
                             const cuuint32_t*, CUtensorMapInterleave, CUtensorMapSwizzle,
                             CUtensorMapL2promotion, CUtensorMapFloatOOBfill);

extern "C" void kernel_launch(void* const* d_in, const int* in_sizes, int n_in,
                              void* d_out, int out_size) {
  const float* kv = nullptr;
  const float* q = nullptr;
  const float* mask = nullptr;
  for (int i = 0; i < n_in; i++) {
    if (in_sizes[i] == 113246208) kv = (const float*)d_in[i];
    else if (in_sizes[i] == 56623104) q = (const float*)d_in[i];
    else if (in_sizes[i] == 2359296) mask = (const float*)d_in[i];
  }
  if (!kv)   kv   = (const float*)d_in[0];
  if (!q)    q    = (const float*)d_in[1];
  if (!mask) mask = (const float*)d_in[2];

  EncodeFn encode = nullptr;
  cudaDriverEntryPointQueryResult qres;
  cudaGetDriverEntryPoint("cuTensorMapEncodeTiled", (void**)&encode,
                          cudaEnableDefault, &qres);

  cuuint64_t strides[2] = {192 * 4ull, (cuuint64_t)HW * 4ull};
  cuuint32_t box[3]     = {8, 8, 32};
  cuuint32_t es[3]      = {1, 1, 1};

  CUtensorMap mapQ{}, mapKV{}, mapO{};
  {
    cuuint64_t dims[3] = {192, 192, 1536};
    encode(&mapQ, CU_TENSOR_MAP_DATA_TYPE_FLOAT32, 3, (void*)q,
           dims, strides, box, es,
           CU_TENSOR_MAP_INTERLEAVE_NONE, CU_TENSOR_MAP_SWIZZLE_NONE,
           CU_TENSOR_MAP_L2_PROMOTION_L2_128B, CU_TENSOR_MAP_FLOAT_OOB_FILL_NONE);
  }
  {
    cuuint64_t dims[3] = {192, 192, 3072};
    encode(&mapKV, CU_TENSOR_MAP_DATA_TYPE_FLOAT32, 3, (void*)kv,
           dims, strides, box, es,
           CU_TENSOR_MAP_INTERLEAVE_NONE, CU_TENSOR_MAP_SWIZZLE_NONE,
           CU_TENSOR_MAP_L2_PROMOTION_L2_128B, CU_TENSOR_MAP_FLOAT_OOB_FILL_NONE);
  }
  {
    cuuint64_t dims[3] = {192, 192, 1536};
    encode(&mapO, CU_TENSOR_MAP_DATA_TYPE_FLOAT32, 3, d_out,
           dims, strides, box, es,
           CU_TENSOR_MAP_INTERLEAVE_NONE, CU_TENSOR_MAP_SWIZZLE_NONE,
           CU_TENSOR_MAP_L2_PROMOTION_L2_128B, CU_TENSOR_MAP_FLOAT_OOB_FILL_NONE);
  }

  repack_mask<<<576, 128>>>(mask);
  cudaFuncSetAttribute(winattn_tma8, cudaFuncAttributeMaxDynamicSharedMemorySize,
                       SMEM_BYTES);
  winattn_tma8<<<27648, 128, SMEM_BYTES>>>(mapQ, mapKV, mapO);
}

// round 17
// speedup vs baseline: 1.3438x; 1.0550x over previous
#include <cuda_runtime.h>
#include <cuda.h>
#include <cuda_bf16.h>
#include <cstdint>

namespace {

constexpr int   HW    = 36864;        // 192*192
constexpr float SCALE = 0.17677669529663687f;  // 1/sqrt(32)

// dynamic smem layout (float/word units)
constexpr int RAW  = 0;      // 2048 words: TMA staging buffer (Q, then K, then V)
constexpr int TQH  = 2048;   // Q fp16 tile: 64 x 20
constexpr int TKH  = 3328;   // K fp16 tile: 64 x 20
constexpr int TVH  = 4608;   // V hi tile: 32 x 36 (1148)
constexpr int TVL  = 5756;
constexpr int MBAR = 6904;   // 2 words
constexpr int SMEM_BYTES = 6906 * 4;  // 27624 B; 6 CTAs/SM (register-bound)

__device__ __forceinline__ uint32_t s2u(const void* p) {
  uint32_t a;
  asm("{ .reg .u64 t; cvta.to.shared.u64 t, %1; cvt.u32.u64 %0, t; }" : "=r"(a) : "l"(p));
  return a;
}
// pack fp16 pair: low half = f16(f0), high half = f16(f1)
__device__ __forceinline__ uint32_t packh2(float f0, float f1) {
  uint32_t r;
  asm("cvt.rn.f16x2.f32 %0, %1, %2;" : "=r"(r) : "f"(f1), "f"(f0));
  return r;
}
// pack truncated-bf16 pair: low half = top16(f0), high half = top16(f1) — one PRMT
__device__ __forceinline__ uint32_t packhi(float f0, float f1) {
  uint32_t r;
  asm("prmt.b32 %0, %1, %2, 0x7632;"
      : "=r"(r) : "r"(__float_as_uint(f0)), "r"(__float_as_uint(f1)));
  return r;
}
// truncate fp32 to bf16-representable value (exact split: f = th(f) + (f - th(f)))
__device__ __forceinline__ float th(float f) {
  return __uint_as_float(__float_as_uint(f) & 0xFFFF0000u);
}
__device__ __forceinline__ uint32_t pack2(float lo, float hi) {
  uint32_t r;
  asm("cvt.rn.bf16x2.f32 %0, %1, %2;" : "=r"(r) : "f"(hi), "f"(lo));
  return r;
}
__device__ __forceinline__ void mma_bf16(float* c, const uint32_t* a,
                                         uint32_t b0, uint32_t b1) {
  asm volatile(
      "mma.sync.aligned.m16n8k16.row.col.f32.bf16.bf16.f32 "
      "{%0,%1,%2,%3}, {%4,%5,%6,%7}, {%8,%9}, {%0,%1,%2,%3};"
      : "+f"(c[0]), "+f"(c[1]), "+f"(c[2]), "+f"(c[3])
      : "r"(a[0]), "r"(a[1]), "r"(a[2]), "r"(a[3]), "r"(b0), "r"(b1));
}
__device__ __forceinline__ void mma_f16(float* c, const uint32_t* a,
                                        uint32_t b0, uint32_t b1) {
  asm volatile(
      "mma.sync.aligned.m16n8k16.row.col.f32.f16.f16.f32 "
      "{%0,%1,%2,%3}, {%4,%5,%6,%7}, {%8,%9}, {%0,%1,%2,%3};"
      : "+f"(c[0]), "+f"(c[1]), "+f"(c[2]), "+f"(c[3])
      : "r"(a[0]), "r"(a[1]), "r"(a[2]), "r"(a[3]), "r"(b0), "r"(b1));
}
__device__ __forceinline__ int qkw(int r, int w) {
  return r * 20 + (w ^ (((r >> 3) & 3) << 2));
}
__device__ __forceinline__ float felem(float4 a, int j) {
  return (j == 0) ? a.x : (j == 1) ? a.y : (j == 2) ? a.z : a.w;
}
__device__ __forceinline__ void bar_init(uint32_t bar, uint32_t cnt) {
  asm volatile("mbarrier.init.shared.b64 [%0], %1;" :: "r"(bar), "r"(cnt) : "memory");
}
__device__ __forceinline__ void bar_expect(uint32_t bar, uint32_t bytes) {
  asm volatile("mbarrier.arrive.expect_tx.shared.b64 _, [%0], %1;"
               :: "r"(bar), "r"(bytes) : "memory");
}
__device__ __forceinline__ void bar_wait(uint32_t bar, uint32_t parity) {
  uint32_t done;
  asm volatile(
      "{\n\t.reg .pred p;\n\t"
      "mbarrier.try_wait.parity.acquire.cta.shared::cta.b64 p, [%1], %2;\n\t"
      "selp.b32 %0, 1, 0, p;\n\t}"
      : "=r"(done) : "r"(bar), "r"(parity) : "memory");
  if (!done) {
    asm volatile(
        "{\n\t.reg .pred P1;\n\t"
        "W_%=:\n\t"
        "mbarrier.try_wait.parity.acquire.cta.shared::cta.b64 P1, [%0], %1, 0x989680;\n\t"
        "@P1 bra.uni D_%=;\n\t"
        "bra.uni W_%=;\n\t"
        "D_%=:\n\t}"
        :: "r"(bar), "r"(parity) : "memory");
  }
}
__device__ __forceinline__ void tma3d(uint32_t dst, const CUtensorMap* map,
                                      int x, int y, int z, uint32_t bar) {
  asm volatile(
      "cp.async.bulk.tensor.3d.shared::cta.global.tile.mbarrier::complete_tx::bytes "
      "[%0], [%1, {%2, %3, %4}], [%5];"
      :: "r"(dst), "l"(map), "r"(x), "r"(y), "r"(z), "r"(bar) : "memory");
}
__device__ __forceinline__ void tma3d_store(const CUtensorMap* map,
                                            int x, int y, int z, uint32_t src) {
  asm volatile(
      "cp.async.bulk.tensor.3d.global.shared::cta.tile.bulk_group "
      "[%0, {%1, %2, %3}], [%4];"
      :: "l"(map), "r"(x), "r"(y), "r"(z), "r"(src) : "memory");
}

}  // namespace

// fragment-ordered mask: [win][warp(4)][j(8)][lane(32)][4 floats]
__device__ float g_maskf[576 * 4096];

__global__ void repack_mask(const float* __restrict__ mask) {
  const int win = blockIdx.x;
  const int tid = threadIdx.x;
  const int wid = tid >> 5;
  const int lid = tid & 31;
  const int g = lid >> 2;
  const int t = lid & 3;
  const float* __restrict__ src = mask + win * 4096;
  float* __restrict__ dst = g_maskf + win * 4096 + wid * 1024;
#pragma unroll
  for (int j = 0; j < 8; j++) {
    const int c0 = 8 * j + 2 * t;
    float4 m;
    m.x = src[(wid * 16 + g) * 64 + c0];
    m.y = src[(wid * 16 + g) * 64 + c0 + 1];
    m.z = src[(wid * 16 + 8 + g) * 64 + c0];
    m.w = src[(wid * 16 + 8 + g) * 64 + c0 + 1];
    *(float4*)(dst + j * 128 + lid * 4) = m;
  }
}

__global__ __launch_bounds__(128, 6) void winattn_tma9(
    const __grid_constant__ CUtensorMap mapQ,
    const __grid_constant__ CUtensorMap mapKV,
    const __grid_constant__ CUtensorMap mapO) {
  extern __shared__ float dyn[];
  float* __restrict__ raw = dyn + RAW;
  uint32_t* __restrict__ sm = (uint32_t*)dyn;   // tiles addressed by absolute word offset

  const int tid = threadIdx.x;
  const int wid = tid >> 5;
  const int lid = tid & 31;

  // block decode: 48 consecutive CTAs (8 b x 6 d) share one mask window (L2 reuse)
  const int blk = blockIdx.x;
  const int win = blk / 48;
  const int rem = blk % 48;
  const int b = rem / 6;
  const int d = rem % 6;
  const int u = win / 24;
  const int v = win % 24;
  const int zc = b * 192 + d * 32;

  const uint32_t mbar = s2u(dyn + MBAR);
  const uint32_t rawA = s2u(raw);
  if (tid == 0) bar_init(mbar, 1);
  __syncthreads();

  // ---------------- phase 1: Q -> raw, convert to fp16 TQH ----------------
  if (tid == 0) {
    bar_expect(mbar, 8192);
    tma3d(rawA, &mapQ, v * 8, u * 8, zc, mbar);
  }
  bar_wait(mbar, 0);
#pragma unroll
  for (int it = 0; it < 2; it++) {
    const int p  = it * 128 + tid;       // 0..255
    const int cw = p >> 4;               // word index = ci/2 (0..15)
    const int h  = (p >> 1) & 7;
    const int wq = p & 1;
    const int n0 = h * 8 + wq * 4;
    const int ro = (2 * cw) * 64 + h * 8 + wq * 4;
    const float4 a0 = *(const float4*)(raw + ro);
    const float4 a1 = *(const float4*)(raw + ro + 64);
#pragma unroll
    for (int j = 0; j < 4; j++) {
      sm[TQH + qkw(n0 + j, cw)] = packh2(felem(a0, j), felem(a1, j));
    }
  }
  __syncthreads();

  // ---------------- phase 2: K -> raw, convert to fp16 TKH ----------------
  if (tid == 0) {
    bar_expect(mbar, 8192);
    tma3d(rawA, &mapKV, v * 8, u * 8, zc, mbar);
  }
  bar_wait(mbar, 1);
#pragma unroll
  for (int it = 0; it < 2; it++) {
    const int p  = it * 128 + tid;
    const int cw = p >> 4;
    const int h  = (p >> 1) & 7;
    const int wq = p & 1;
    const int n0 = h * 8 + wq * 4;
    const int ro = (2 * cw) * 64 + h * 8 + wq * 4;
    const float4 a0 = *(const float4*)(raw + ro);
    const float4 a1 = *(const float4*)(raw + ro + 64);
#pragma unroll
    for (int j = 0; j < 4; j++) {
      sm[TKH + qkw(n0 + j, cw)] = packh2(felem(a0, j), felem(a1, j));
    }
  }
  __syncthreads();

  // ---------------- phase 3: V -> raw, convert to TVH/TVL (bf16 hi/lo) ----------
  if (tid == 0) {
    bar_expect(mbar, 8192);
    tma3d(rawA, &mapKV, v * 8, u * 8, 1536 + zc, mbar);
  }
  bar_wait(mbar, 0);
#pragma unroll
  for (int it = 0; it < 4; it++) {
    const int p  = it * 128 + tid;       // 0..511
    const int ci = p >> 4;
    const int h  = (p >> 1) & 7;
    const int wq = p & 1;
    const int n0 = h * 8 + wq * 4;
    const float4 a = *(const float4*)(raw + ci * 64 + h * 8 + wq * 4);
    uint2 hp, lp;
    hp.x = packhi(a.x, a.y);
    hp.y = packhi(a.z, a.w);
    lp.x = pack2(a.x - th(a.x), a.y - th(a.y));
    lp.y = pack2(a.z - th(a.z), a.w - th(a.w));
    *(uint2*)&sm[TVH + ci * 36 + (n0 >> 1)] = hp;
    *(uint2*)&sm[TVL + ci * 36 + (n0 >> 1)] = lp;
  }
  __syncthreads();

  const int g  = lid >> 2;   // 0..7
  const int t  = lid & 3;    // 0..3
  const int m0 = wid * 16;

  // ================= A-fragments (fp16 Q) ========================================
  uint32_t aq[2][4];
#pragma unroll
  for (int ks = 0; ks < 2; ks++) {
    aq[ks][0] = sm[TQH + qkw(m0 + g,     ks * 8 + t)];
    aq[ks][1] = sm[TQH + qkw(m0 + g + 8, ks * 8 + t)];
    aq[ks][2] = sm[TQH + qkw(m0 + g,     ks * 8 + 4 + t)];
    aq[ks][3] = sm[TQH + qkw(m0 + g + 8, ks * 8 + 4 + t)];
  }

  // ================= QK^T (fp16 single product) ==================================
  float c[8][4];
#pragma unroll
  for (int j = 0; j < 8; j++)
#pragma unroll
    for (int i = 0; i < 4; i++) c[j][i] = 0.f;

#pragma unroll
  for (int j = 0; j < 8; j++) {          // n-tile: cols 8j..8j+7
    const int rb = j * 8 + g;
#pragma unroll
    for (int ks = 0; ks < 2; ks++) {
      const uint32_t b0 = sm[TKH + qkw(rb, ks * 8 + t)];
      const uint32_t b1 = sm[TKH + qkw(rb, ks * 8 + 4 + t)];
      mma_f16(c[j], aq[ks], b0, b1);
    }
  }

  // ===== softmax: mask from fragment-ordered global buffer (dense LDG.128) ======
  const float4* __restrict__ mw =
      (const float4*)(g_maskf + win * 4096 + wid * 1024) + lid;
  float sum0 = 0.f, sum1 = 0.f;
#pragma unroll
  for (int j = 0; j < 8; j++) {
    const float4 m = mw[j * 32];
    float e;
    e = __expf(fmaf(c[j][0], SCALE, m.x)); c[j][0] = e; sum0 += e;
    e = __expf(fmaf(c[j][1], SCALE, m.y)); c[j][1] = e; sum0 += e;
    e = __expf(fmaf(c[j][2], SCALE, m.z)); c[j][2] = e; sum1 += e;
    e = __expf(fmaf(c[j][3], SCALE, m.w)); c[j][3] = e; sum1 += e;
  }
  sum0 += __shfl_xor_sync(0xffffffffu, sum0, 1);
  sum0 += __shfl_xor_sync(0xffffffffu, sum0, 2);
  sum1 += __shfl_xor_sync(0xffffffffu, sum1, 1);
  sum1 += __shfl_xor_sync(0xffffffffu, sum1, 2);
  const float inv0 = 1.0f / sum0;
  const float inv1 = 1.0f / sum1;

  // P fragments (S accumulator layout == PV A-fragment layout), truncated bf16 hi/lo
  uint32_t aph[4][4], apl[4][4];
#pragma unroll
  for (int ks = 0; ks < 4; ks++) {
    const float* p0 = c[2 * ks];
    const float* p1 = c[2 * ks + 1];
    aph[ks][0] = packhi(p0[0], p0[1]);
    aph[ks][1] = packhi(p0[2], p0[3]);
    aph[ks][2] = packhi(p1[0], p1[1]);
    aph[ks][3] = packhi(p1[2], p1[3]);
    apl[ks][0] = pack2(p0[0] - th(p0[0]), p0[1] - th(p0[1]));
    apl[ks][1] = pack2(p0[2] - th(p0[2]), p0[3] - th(p0[3]));
    apl[ks][2] = pack2(p1[0] - th(p1[0]), p1[1] - th(p1[1]));
    apl[ks][3] = pack2(p1[2] - th(p1[2]), p1[3] - th(p1[3]));
  }
  __syncthreads();   // all warps past Q/K tile reads before sO overwrites them

  // ================= O = P V (bf16 3-product) ====================================
  float o[4][4];
#pragma unroll
  for (int jn = 0; jn < 4; jn++)
#pragma unroll
    for (int i = 0; i < 4; i++) o[jn][i] = 0.f;

#pragma unroll
  for (int jn = 0; jn < 4; jn++) {       // channel tile 8jn..8jn+7
    const int rv = (jn * 8 + g) * 36;
#pragma unroll
    for (int ks = 0; ks < 4; ks++) {     // key step 16ks..16ks+15
      const uint32_t bh0 = sm[TVH + rv + ks * 8 + t];
      const uint32_t bh1 = sm[TVH + rv + ks * 8 + 4 + t];
      const uint32_t bl0 = sm[TVL + rv + ks * 8 + t];
      const uint32_t bl1 = sm[TVL + rv + ks * 8 + 4 + t];
      mma_bf16(o[jn], aph[ks], bh0, bh1);
      mma_bf16(o[jn], aph[ks], bl0, bl1);
      mma_bf16(o[jn], apl[ks], bh0, bh1);
    }
  }

  // ===== stage O dense [c][h][w] fp32 (plain layout, TMA store source) ===========
  float* __restrict__ sO = dyn + TQH;    // words [2048..4096), Q/K tiles dead
#pragma unroll
  for (int jn = 0; jn < 4; jn++) {
    const int ch = jn * 8 + 2 * t;
#pragma unroll
    for (int bb = 0; bb < 2; bb++) {
      sO[(ch + bb) * 64 + m0 + g]     = o[jn][bb] * inv0;
      sO[(ch + bb) * 64 + m0 + g + 8] = o[jn][2 + bb] * inv1;
    }
  }
  __syncthreads();

  // ================= TMA store O =================================================
  if (tid == 0) {
    asm volatile("fence.proxy.async.shared::cta;" ::: "memory");
    tma3d_store(&mapO, v * 8, u * 8, zc, s2u(sO));
    asm volatile("cp.async.bulk.commit_group;" ::: "memory");
    asm volatile("cp.async.bulk.wait_group 0;" ::: "memory");
  }
}

typedef CUresult (*EncodeFn)(CUtensorMap*, CUtensorMapDataType, cuuint32_t, void*,
                             const cuuint64_t*, const cuuint64_t*, const cuuint32_t*,
                             const cuuint32_t*, CUtensorMapInterleave, CUtensorMapSwizzle,
                             CUtensorMapL2promotion, CUtensorMapFloatOOBfill);

extern "C" void kernel_launch(void* const* d_in, const int* in_sizes, int n_in,
                              void* d_out, int out_size) {
  const float* kv = nullptr;
  const float* q = nullptr;
  const float* mask = nullptr;
  for (int i = 0; i < n_in; i++) {
    if (in_sizes[i] == 113246208) kv = (const float*)d_in[i];
    else if (in_sizes[i] == 56623104) q = (const float*)d_in[i];
    else if (in_sizes[i] == 2359296) mask = (const float*)d_in[i];
  }
  if (!kv)   kv   = (const float*)d_in[0];
  if (!q)    q    = (const float*)d_in[1];
  if (!mask) mask = (const float*)d_in[2];

  EncodeFn encode = nullptr;
  cudaDriverEntryPointQueryResult qres;
  cudaGetDriverEntryPoint("cuTensorMapEncodeTiled", (void**)&encode,
                          cudaEnableDefault, &qres);

  cuuint64_t strides[2] = {192 * 4ull, (cuuint64_t)HW * 4ull};
  cuuint32_t box[3]     = {8, 8, 32};
  cuuint32_t es[3]      = {1, 1, 1};

  CUtensorMap mapQ{}, mapKV{}, mapO{};
  {
    cuuint64_t dims[3] = {192, 192, 1536};
    encode(&mapQ, CU_TENSOR_MAP_DATA_TYPE_FLOAT32, 3, (void*)q,
           dims, strides, box, es,
           CU_TENSOR_MAP_INTERLEAVE_NONE, CU_TENSOR_MAP_SWIZZLE_NONE,
           CU_TENSOR_MAP_L2_PROMOTION_L2_128B, CU_TENSOR_MAP_FLOAT_OOB_FILL_NONE);
  }
  {
    cuuint64_t dims[3] = {192, 192, 3072};
    encode(&mapKV, CU_TENSOR_MAP_DATA_TYPE_FLOAT32, 3, (void*)kv,
           dims, strides, box, es,
           CU_TENSOR_MAP_INTERLEAVE_NONE, CU_TENSOR_MAP_SWIZZLE_NONE,
           CU_TENSOR_MAP_L2_PROMOTION_L2_128B, CU_TENSOR_MAP_FLOAT_OOB_FILL_NONE);
  }
  {
    cuuint64_t dims[3] = {192, 192, 1536};
    encode(&mapO, CU_TENSOR_MAP_DATA_TYPE_FLOAT32, 3, d_out,
           dims, strides, box, es,
           CU_TENSOR_MAP_INTERLEAVE_NONE, CU_TENSOR_MAP_SWIZZLE_NONE,
           CU_TENSOR_MAP_L2_PROMOTION_L2_128B, CU_TENSOR_MAP_FLOAT_OOB_FILL_NONE);
  }

  repack_mask<<<576, 128>>>(mask);
  cudaFuncSetAttribute(winattn_tma9, cudaFuncAttributeMaxDynamicSharedMemorySize,
                       SMEM_BYTES);
  winattn_tma9<<<27648, 128, SMEM_BYTES>>>(mapQ, mapKV, mapO);
}